// round 11
// baseline (speedup 1.0000x reference)
#include <cuda_runtime.h>
#include <math.h>

#define NB 30
#define TPB 256
#define GRID_MAIN 444   // 3 blocks/SM on 148 SMs; launch_bounds(256,3) guarantees co-residency
#define HALF 222        // blocks per array in both column phases
#define FIN_BLOCKS 80   // 64 hist-MI + 16 mi_us

// ---------------- device scratch (zero-init; kernel restores zeros for graph replay) ----------------
__device__ unsigned int g_hist[32][NB * NB];
__device__ unsigned int g_maxkey[33];   // max of fenc(v)   -> mx = fdec(key)
__device__ unsigned int g_minkey[33];   // max of ~fenc(v)  -> mn = fdec(~key)
__device__ double g_l1sum;
__device__ double g_mi_hist;
__device__ double g_mi_us;
__device__ unsigned int g_arrive1;
__device__ unsigned int g_arrive2;
__device__ unsigned int g_done;
__device__ unsigned int g_hdone[32];

static __device__ __forceinline__ unsigned fenc(float f) {
    unsigned u = __float_as_uint(f);
    return (u & 0x80000000u) ? ~u : (u | 0x80000000u);
}
static __device__ __forceinline__ float fdec(unsigned u) {
    return __uint_as_float((u & 0x80000000u) ? (u ^ 0x80000000u) : ~u);
}
static __device__ __forceinline__ float edge_at(float mn, float delta, int j) {
    return __fadd_rn(mn, __fmul_rn((float)j, delta));
}
static __device__ __forceinline__ void load_row16(const float* a, int r, float* v) {
    const float4* p = (const float4*)(a + (size_t)r * 16);
    float4 t;
    t = p[0]; v[0]  = t.x; v[1]  = t.y; v[2]  = t.z; v[3]  = t.w;
    t = p[1]; v[4]  = t.x; v[5]  = t.y; v[6]  = t.z; v[7]  = t.w;
    t = p[2]; v[8]  = t.x; v[9]  = t.y; v[10] = t.z; v[11] = t.w;
    t = p[3]; v[12] = t.x; v[13] = t.y; v[14] = t.z; v[15] = t.w;
}

// mi_us labelize (exact linspace binning: only 16 samples -> boundary errors matter)
static __device__ void labelize16(const float* v, int* lab) {
    float mn = v[0], mx = v[0];
#pragma unroll
    for (int d = 1; d < 16; d++) { mn = fminf(mn, v[d]); mx = fmaxf(mx, v[d]); }
    float d29 = __fdiv_rn(__fsub_rn(mx, mn), 29.0f);
    float iv = 1.0f / d29;
#pragma unroll
    for (int d = 0; d < 16; d++) {
        float x = v[d];
        int j = (int)((x - mn) * iv);
        j = j < 0 ? 0 : (j > 29 ? 29 : j);
        while (j < 29 && edge_at(mn, d29, j + 1) <= x) j++;
        while (j > 0 && edge_at(mn, d29, j) > x) j--;
        lab[d] = j + 1;
    }
}

// ---------------- single fused kernel ----------------
__global__ void __launch_bounds__(TPB, 3) k_main(const float* __restrict__ u,
                                                 const float* __restrict__ s,
                                                 const float* __restrict__ yt,
                                                 const float* __restrict__ yp,
                                                 int n, float n_total,
                                                 float* __restrict__ out) {
    __shared__ unsigned sh[16 * 15 * NB];  // 28.8 KB: phase-2 histograms (reused in phase 3)
    __shared__ unsigned smx[16], smnk[16];
    int bid = blockIdx.x;
    int tid = threadIdx.x;

    // zero phase-2 histograms up front (independent of min/max -> off the post-barrier path)
    for (int i = tid; i < 16 * 15 * NB; i += TPB) sh[i] = 0u;

    const float* a = (bid < HALF) ? u : s;
    int base = (bid < HALF) ? 0 : 16;
    int pb = (bid < HALF) ? bid : bid - HALF;
    const int stride = HALF * TPB;  // 56832

    // ---------- phase 1a: y_pred minmax + L1, thin slice on ALL blocks (float4) ----------
    {
        int n4 = n >> 2;
        float mn = __int_as_float(0x7F800000), mx = __int_as_float(0xFF800000);
        double acc = 0.0;
        const float4* yp4 = (const float4*)yp;
        const float4* yt4 = (const float4*)yt;
        const int ystride = GRID_MAIN * TPB;
        for (int i = bid * TPB + tid; i < n4; i += ystride) {
            float4 p = yp4[i];
            float4 t = yt4[i];
            mn = fminf(mn, fminf(fminf(p.x, p.y), fminf(p.z, p.w)));
            mx = fmaxf(mx, fmaxf(fmaxf(p.x, p.y), fmaxf(p.z, p.w)));
            acc += (double)(fabsf(t.x - p.x) + fabsf(t.y - p.y) + fabsf(t.z - p.z) + fabsf(t.w - p.w));
        }
        for (int i = (n4 << 2) + bid * TPB + tid; i < n; i += ystride) {
            float v = yp[i];
            mn = fminf(mn, v); mx = fmaxf(mx, v);
            acc += (double)fabsf(yt[i] - v);
        }
#pragma unroll
        for (int o = 16; o; o >>= 1) {
            mn = fminf(mn, __shfl_down_sync(0xFFFFFFFFu, mn, o));
            mx = fmaxf(mx, __shfl_down_sync(0xFFFFFFFFu, mx, o));
            acc += __shfl_down_sync(0xFFFFFFFFu, acc, o);
        }
        if ((tid & 31) == 0) {
            atomicMax(&g_maxkey[32], fenc(mx));
            atomicMax(&g_minkey[32], ~fenc(mn));
            atomicAdd(&g_l1sum, acc);
        }
    }

    // ---------- phase 1b: per-column min/max, 222 blocks per array, 2-row unroll ----------
    {
        float mn[16], mx[16];
#pragma unroll
        for (int c = 0; c < 16; c++) { mn[c] = __int_as_float(0x7F800000); mx[c] = __int_as_float(0xFF800000); }
        int r = pb * TPB + tid;
        for (; r + stride < n; r += 2 * stride) {
            float va[16], vb[16];
            load_row16(a, r, va);
            load_row16(a, r + stride, vb);
#pragma unroll
            for (int c = 0; c < 16; c++) {
                mn[c] = fminf(mn[c], fminf(va[c], vb[c]));
                mx[c] = fmaxf(mx[c], fmaxf(va[c], vb[c]));
            }
        }
        for (; r < n; r += stride) {
            float va[16];
            load_row16(a, r, va);
#pragma unroll
            for (int c = 0; c < 16; c++) { mn[c] = fminf(mn[c], va[c]); mx[c] = fmaxf(mx[c], va[c]); }
        }
        if (tid < 16) { smx[tid] = 0u; smnk[tid] = 0u; }
        __syncthreads();
#pragma unroll
        for (int c = 0; c < 16; c++) {
            atomicMax(&smx[c], fenc(mx[c]));
            atomicMax(&smnk[c], ~fenc(mn[c]));
        }
        __syncthreads();
        if (tid < 16) {
            atomicMax(&g_maxkey[base + tid], smx[tid]);
            atomicMax(&g_minkey[base + tid], smnk[tid]);
        }
    }

    // ---------- barrier 1 ----------
    __threadfence();
    __syncthreads();
    if (tid == 0) {
        atomicAdd(&g_arrive1, 1u);
        while (atomicAdd(&g_arrive1, 0u) < GRID_MAIN) __nanosleep(64);
    }
    __syncthreads();

    // ---------- phase 2: histograms (2-row unrolled; sh already zeroed) ----------
    {
        float inv[16], ninv[16];
#pragma unroll
        for (int c = 0; c < 16; c++) {
            float lo = fdec(~g_minkey[base + c]);
            float hi = fdec(g_maxkey[base + c]);
            float iv = 1.0f / __fdiv_rn(__fsub_rn(hi, lo), 30.0f);
            inv[c] = iv;
            ninv[c] = -lo * iv;
        }
        float ymn = fdec(~g_minkey[32]);
        float yiv = 1.0f / __fdiv_rn(__fsub_rn(fdec(g_maxkey[32]), ymn), 30.0f);
        float yni = -ymn * yiv;

        int r = pb * TPB + tid;
        for (; r + stride < n; r += 2 * stride) {
            float ya = __ldg(yp + r);
            float yb = __ldg(yp + r + stride);
            float va[16], vb[16];
            load_row16(a, r, va);
            load_row16(a, r + stride, vb);
            int iya = min((int)fmaf(ya, yiv, yni), 29);
            int iyb = min((int)fmaf(yb, yiv, yni), 29);
            unsigned inca = (iya & 1) ? 0x10000u : 1u;
            unsigned incb = (iyb & 1) ? 0x10000u : 1u;
            int yha = iya >> 1, yhb = iyb >> 1;
#pragma unroll
            for (int c = 0; c < 16; c++) {
                int ixa = min((int)fmaf(va[c], inv[c], ninv[c]), 29);
                int ixb = min((int)fmaf(vb[c], inv[c], ninv[c]), 29);
                atomicAdd(&sh[c * (15 * NB) + ixa * 15 + yha], inca);
                atomicAdd(&sh[c * (15 * NB) + ixb * 15 + yhb], incb);
            }
        }
        for (; r < n; r += stride) {
            float va[16];
            load_row16(a, r, va);
            int iy = min((int)fmaf(__ldg(yp + r), yiv, yni), 29);
            unsigned inc = (iy & 1) ? 0x10000u : 1u;
            int yh = iy >> 1;
#pragma unroll
            for (int c = 0; c < 16; c++) {
                int ix = min((int)fmaf(va[c], inv[c], ninv[c]), 29);
                atomicAdd(&sh[c * (15 * NB) + ix * 15 + yh], inc);
            }
        }
        __syncthreads();
        for (int w = tid; w < 16 * 15 * NB; w += TPB) {
            unsigned x = sh[w];
            if (!x) continue;
            int c = w / (15 * NB), rr = w % (15 * NB);
            int ix = rr / 15, iy2 = (rr % 15) * 2;
            unsigned lo = x & 0xFFFFu, hi = x >> 16;
            if (lo) atomicAdd(&g_hist[base + c][ix * NB + iy2], lo);
            if (hi) atomicAdd(&g_hist[base + c][ix * NB + iy2 + 1], hi);
        }
    }

    // ---------- barrier 2 (blocks >= FIN_BLOCKS arrive and exit) ----------
    __threadfence();
    __syncthreads();
    if (tid == 0) atomicAdd(&g_arrive2, 1u);
    if (bid >= FIN_BLOCKS) return;
    if (tid == 0) {
        while (atomicAdd(&g_arrive2, 0u) < GRID_MAIN) __nanosleep(64);
    }
    __syncthreads();

    // ---------- phase 3: finalize (blocks 0..79) ----------
    if (bid < 64) {
        int h = bid >> 1;
        int half = bid & 1;
        unsigned* H = g_hist[h];
        float* rs = (float*)sh;
        float* cs = (float*)sh + 32;
        if (tid < NB) {
            unsigned ssum = 0;
#pragma unroll
            for (int j = 0; j < NB; j++) ssum += H[tid * NB + j];
            rs[tid] = (float)ssum;
        } else if (tid >= 32 && tid < 32 + NB) {
            int c = tid - 32;
            unsigned ssum = 0;
#pragma unroll
            for (int i = 0; i < NB; i++) ssum += H[i * NB + c];
            cs[c] = (float)ssum;
        }
        __syncthreads();
        double acc = 0.0;
        int begin = half * 450;
        for (int idx = begin + tid; idx < begin + 450; idx += TPB) {
            int i = idx / NB, j = idx % NB;
            float cnt = (float)H[idx];
            float pxy = (cnt > 0.f) ? __fdiv_rn(cnt, n_total) : 1e-10f;
            float px  = (rs[i] > 0.f) ? __fdiv_rn(rs[i], n_total) : 1e-10f;
            float py  = (cs[j] > 0.f) ? __fdiv_rn(cs[j], n_total) : 1e-10f;
            acc += (double)(pxy * logf(pxy / (px * py)));
        }
#pragma unroll
        for (int o = 16; o; o >>= 1) acc += __shfl_down_sync(0xFFFFFFFFu, acc, o);
        double* wacc = (double*)(sh + 64);
        __shared__ int zeroer;
        if ((tid & 31) == 0) wacc[tid >> 5] = acc;
        __syncthreads();
        if (tid == 0) {
            double sum = 0.0;
            for (int w = 0; w < TPB / 32; w++) sum += wacc[w];
            atomicAdd(&g_mi_hist, sum);
            zeroer = (atomicAdd(&g_hdone[h], 1u) == 1u);  // second finisher resets this hist
        }
        __syncthreads();
        if (zeroer) {
            for (int w = tid; w < NB * NB; w += TPB) H[w] = 0u;
            if (tid == 0) g_hdone[h] = 0u;
        }
    } else {
        int i = bid - 64;
        int* slu = (int*)sh;
        int* sls = (int*)sh + 16;
        if (tid == 0) {
            float uv[16];
#pragma unroll
            for (int d = 0; d < 16; d++) uv[d] = u[i * 16 + d];
            labelize16(uv, slu);
        } else if (tid == 32) {
            float sv[16];
#pragma unroll
            for (int d = 0; d < 16; d++) sv[d] = s[i * 16 + d];
            labelize16(sv, sls);
        }
        __syncthreads();
        float term = 0.f;
        if (tid < 16) {
            int lj = slu[tid], sj = sls[tid];
            int a2 = 0, b2 = 0, c2 = 0;
#pragma unroll
            for (int k = 0; k < 16; k++) {
                int eu = (slu[k] == lj);
                int es = (sls[k] == sj);
                a2 += eu; b2 += es; c2 += eu & es;
            }
            term = logf((float)(c2 * 16) / (float)(a2 * b2));
        }
        if (tid < 32) {
            double acc = (double)term;
#pragma unroll
            for (int o = 16; o; o >>= 1) acc += __shfl_down_sync(0xFFFFFFFFu, acc, o);
            if (tid == 0) atomicAdd(&g_mi_us, acc * (1.0 / 16.0));
        }
    }

    // ---------- combine + full state reset (last fin block) ----------
    __threadfence();
    __syncthreads();
    if (tid == 0) {
        unsigned ticket = atomicAdd(&g_done, 1u);
        if (ticket == FIN_BLOCKS - 1u) {
            out[0] = (float)(g_l1sum / (double)n_total + 0.1 * g_mi_hist - 0.05 * g_mi_us);
            for (int i = 0; i < 33; i++) { g_maxkey[i] = 0u; g_minkey[i] = 0u; }
            g_l1sum = 0.0; g_mi_hist = 0.0; g_mi_us = 0.0;
            g_arrive1 = 0u; g_arrive2 = 0u;
            __threadfence();
            g_done = 0u;
        }
    }
}

// ---------------- launch ----------------
extern "C" void kernel_launch(void* const* d_in, const int* in_sizes, int n_in,
                              void* d_out, int out_size) {
    const float* y_true = (const float*)d_in[0];
    const float* y_pred = (const float*)d_in[1];
    const float* u_vec  = (const float*)d_in[4];
    const float* s_vec  = (const float*)d_in[5];
    int n = in_sizes[0];

    k_main<<<GRID_MAIN, TPB>>>(u_vec, s_vec, y_true, y_pred, n, (float)n, (float*)d_out);
}

// round 12
// speedup vs baseline: 1.0732x; 1.0732x over previous
#include <cuda_runtime.h>
#include <math.h>

#define NB 30
#define GRID_MAIN 444   // 3 blocks/SM on 148 SMs; launch_bounds(256,3) guarantees co-residency
#define FIN_BLOCKS 80   // 64 hist-MI + 16 mi_us

// ---------------- device scratch (zero-init; kernel restores zeros for graph replay) ----------------
__device__ unsigned int g_hist[32][NB * NB];
__device__ unsigned int g_maxkey[33];   // max of fenc(v)   -> mx = fdec(key)
__device__ unsigned int g_minkey[33];   // max of ~fenc(v)  -> mn = fdec(~key)
__device__ double g_l1sum;
__device__ double g_mi_hist;
__device__ double g_mi_us;
__device__ unsigned int g_arrive1;
__device__ unsigned int g_arrive2;
__device__ unsigned int g_done;
__device__ unsigned int g_hdone[32];

static __device__ __forceinline__ unsigned fenc(float f) {
    unsigned u = __float_as_uint(f);
    return (u & 0x80000000u) ? ~u : (u | 0x80000000u);
}
static __device__ __forceinline__ float fdec(unsigned u) {
    return __uint_as_float((u & 0x80000000u) ? (u ^ 0x80000000u) : ~u);
}
static __device__ __forceinline__ float edge_at(float mn, float delta, int j) {
    return __fadd_rn(mn, __fmul_rn((float)j, delta));
}
static __device__ __forceinline__ void load_row16(const float* a, int r, float* v) {
    const float4* p = (const float4*)(a + (size_t)r * 16);
    float4 t;
    t = p[0]; v[0]  = t.x; v[1]  = t.y; v[2]  = t.z; v[3]  = t.w;
    t = p[1]; v[4]  = t.x; v[5]  = t.y; v[6]  = t.z; v[7]  = t.w;
    t = p[2]; v[8]  = t.x; v[9]  = t.y; v[10] = t.z; v[11] = t.w;
    t = p[3]; v[12] = t.x; v[13] = t.y; v[14] = t.z; v[15] = t.w;
}

// mi_us labelize (exact linspace binning: only 16 samples -> boundary errors matter)
static __device__ void labelize16(const float* v, int* lab) {
    float mn = v[0], mx = v[0];
#pragma unroll
    for (int d = 1; d < 16; d++) { mn = fminf(mn, v[d]); mx = fmaxf(mx, v[d]); }
    float d29 = __fdiv_rn(__fsub_rn(mx, mn), 29.0f);
    float iv = 1.0f / d29;
#pragma unroll
    for (int d = 0; d < 16; d++) {
        float x = v[d];
        int j = (int)((x - mn) * iv);
        j = j < 0 ? 0 : (j > 29 ? 29 : j);
        while (j < 29 && edge_at(mn, d29, j + 1) <= x) j++;
        while (j > 0 && edge_at(mn, d29, j) > x) j--;
        lab[d] = j + 1;
    }
}

// ---------------- single fused kernel ----------------
__global__ void __launch_bounds__(256, 3) k_main(const float* __restrict__ u,
                                                 const float* __restrict__ s,
                                                 const float* __restrict__ yt,
                                                 const float* __restrict__ yp,
                                                 int n, float n_total,
                                                 float* __restrict__ out) {
    __shared__ unsigned sh[16 * 15 * NB];  // 28.8 KB: phase-2 histograms (reused in phase 3)
    __shared__ unsigned smx[16], smnk[16];
    int bid = blockIdx.x;
    int tid = threadIdx.x;

    // hoisted: zero phase-2 histograms up front, overlapping phase-1 global-load latency
    for (int i = tid; i < 16 * 15 * NB; i += blockDim.x) sh[i] = 0u;

    // ---------- phase 1: min/max + L1 ----------
    if (bid < 384) {
        // bid 0..191: u columns; 192..383: s columns.  2-row unrolled for MLP.
        const float* a = (bid < 192) ? u : s;
        int base = (bid < 192) ? 0 : 16;
        int pb = (bid < 192) ? bid : bid - 192;
        const int stride = 192 * 256;
        float mn[16], mx[16];
#pragma unroll
        for (int c = 0; c < 16; c++) { mn[c] = __int_as_float(0x7F800000); mx[c] = __int_as_float(0xFF800000); }
        int r = pb * 256 + tid;
        for (; r + stride < n; r += 2 * stride) {
            float va[16], vb[16];
            load_row16(a, r, va);
            load_row16(a, r + stride, vb);
#pragma unroll
            for (int c = 0; c < 16; c++) {
                mn[c] = fminf(mn[c], fminf(va[c], vb[c]));
                mx[c] = fmaxf(mx[c], fmaxf(va[c], vb[c]));
            }
        }
        for (; r < n; r += stride) {
            float va[16];
            load_row16(a, r, va);
#pragma unroll
            for (int c = 0; c < 16; c++) { mn[c] = fminf(mn[c], va[c]); mx[c] = fmaxf(mx[c], va[c]); }
        }
        if (tid < 16) { smx[tid] = 0u; smnk[tid] = 0u; }
        __syncthreads();
#pragma unroll
        for (int c = 0; c < 16; c++) {
            atomicMax(&smx[c], fenc(mx[c]));
            atomicMax(&smnk[c], ~fenc(mn[c]));
        }
        __syncthreads();
        if (tid < 16) {
            atomicMax(&g_maxkey[base + tid], smx[tid]);
            atomicMax(&g_minkey[base + tid], smnk[tid]);
        }
    } else {
        // bid 384..443: y_pred minmax + L1 (60 blocks), float4 vectorized
        int pb = bid - 384;
        const int stride4 = 60 * 256;
        int n4 = n >> 2;
        float mn = __int_as_float(0x7F800000), mx = __int_as_float(0xFF800000);
        double acc = 0.0;
        const float4* yp4 = (const float4*)yp;
        const float4* yt4 = (const float4*)yt;
        for (int i = pb * 256 + tid; i < n4; i += stride4) {
            float4 p = yp4[i];
            float4 t = yt4[i];
            mn = fminf(mn, fminf(fminf(p.x, p.y), fminf(p.z, p.w)));
            mx = fmaxf(mx, fmaxf(fmaxf(p.x, p.y), fmaxf(p.z, p.w)));
            float s4 = fabsf(t.x - p.x) + fabsf(t.y - p.y) + fabsf(t.z - p.z) + fabsf(t.w - p.w);
            acc += (double)s4;
        }
        // scalar tail (n not multiple of 4)
        for (int i = (n4 << 2) + pb * 256 + tid; i < n; i += stride4) {
            float v = yp[i];
            mn = fminf(mn, v); mx = fmaxf(mx, v);
            acc += (double)fabsf(yt[i] - v);
        }
#pragma unroll
        for (int o = 16; o; o >>= 1) {
            mn = fminf(mn, __shfl_down_sync(0xFFFFFFFFu, mn, o));
            mx = fmaxf(mx, __shfl_down_sync(0xFFFFFFFFu, mx, o));
            acc += __shfl_down_sync(0xFFFFFFFFu, acc, o);
        }
        if ((tid & 31) == 0) {
            atomicMax(&g_maxkey[32], fenc(mx));
            atomicMax(&g_minkey[32], ~fenc(mn));
            atomicAdd(&g_l1sum, acc);
        }
    }

    // ---------- barrier 1 ----------
    __threadfence();
    __syncthreads();
    if (tid == 0) {
        atomicAdd(&g_arrive1, 1u);
        while (atomicAdd(&g_arrive1, 0u) < GRID_MAIN) __nanosleep(64);
    }
    __syncthreads();

    // ---------- phase 2: histograms (2-row unrolled; sh already zeroed in prologue) ----------
    {
        const float* a = (bid < 222) ? u : s;
        int hbase = (bid < 222) ? 0 : 16;
        int pb = (bid < 222) ? bid : bid - 222;
        const int stride = 222 * 256;

        float inv[16], ninv[16];
#pragma unroll
        for (int c = 0; c < 16; c++) {
            float lo = fdec(~g_minkey[hbase + c]);
            float hi = fdec(g_maxkey[hbase + c]);
            float iv = 1.0f / __fdiv_rn(__fsub_rn(hi, lo), 30.0f);
            inv[c] = iv;
            ninv[c] = -lo * iv;
        }
        float ymn = fdec(~g_minkey[32]);
        float yiv = 1.0f / __fdiv_rn(__fsub_rn(fdec(g_maxkey[32]), ymn), 30.0f);
        float yni = -ymn * yiv;

        int r = pb * 256 + tid;
        for (; r + stride < n; r += 2 * stride) {
            float ya = __ldg(yp + r);
            float yb = __ldg(yp + r + stride);
            float va[16], vb[16];
            load_row16(a, r, va);
            load_row16(a, r + stride, vb);
            int iya = min((int)fmaf(ya, yiv, yni), 29);
            int iyb = min((int)fmaf(yb, yiv, yni), 29);
            unsigned inca = (iya & 1) ? 0x10000u : 1u;
            unsigned incb = (iyb & 1) ? 0x10000u : 1u;
            int yha = iya >> 1, yhb = iyb >> 1;
#pragma unroll
            for (int c = 0; c < 16; c++) {
                int ixa = min((int)fmaf(va[c], inv[c], ninv[c]), 29);
                int ixb = min((int)fmaf(vb[c], inv[c], ninv[c]), 29);
                atomicAdd(&sh[c * (15 * NB) + ixa * 15 + yha], inca);
                atomicAdd(&sh[c * (15 * NB) + ixb * 15 + yhb], incb);
            }
        }
        for (; r < n; r += stride) {
            float va[16];
            load_row16(a, r, va);
            int iy = min((int)fmaf(__ldg(yp + r), yiv, yni), 29);
            unsigned inc = (iy & 1) ? 0x10000u : 1u;
            int yh = iy >> 1;
#pragma unroll
            for (int c = 0; c < 16; c++) {
                int ix = min((int)fmaf(va[c], inv[c], ninv[c]), 29);
                atomicAdd(&sh[c * (15 * NB) + ix * 15 + yh], inc);
            }
        }
        __syncthreads();
        for (int w = tid; w < 16 * 15 * NB; w += blockDim.x) {
            unsigned x = sh[w];
            if (!x) continue;
            int c = w / (15 * NB), rr = w % (15 * NB);
            int ix = rr / 15, iy2 = (rr % 15) * 2;
            unsigned lo = x & 0xFFFFu, hi = x >> 16;
            if (lo) atomicAdd(&g_hist[hbase + c][ix * NB + iy2], lo);
            if (hi) atomicAdd(&g_hist[hbase + c][ix * NB + iy2 + 1], hi);
        }
    }

    // ---------- barrier 2 (blocks >= FIN_BLOCKS arrive and exit) ----------
    __threadfence();
    __syncthreads();
    if (tid == 0) atomicAdd(&g_arrive2, 1u);
    if (bid >= FIN_BLOCKS) return;
    if (tid == 0) {
        while (atomicAdd(&g_arrive2, 0u) < GRID_MAIN) __nanosleep(64);
    }
    __syncthreads();

    // ---------- phase 3: finalize (blocks 0..79) ----------
    if (bid < 64) {
        int h = bid >> 1;
        int half = bid & 1;
        unsigned* H = g_hist[h];
        float* rs = (float*)sh;
        float* cs = (float*)sh + 32;
        if (tid < NB) {
            unsigned ssum = 0;
#pragma unroll
            for (int j = 0; j < NB; j++) ssum += H[tid * NB + j];
            rs[tid] = (float)ssum;
        } else if (tid >= 32 && tid < 32 + NB) {
            int c = tid - 32;
            unsigned ssum = 0;
#pragma unroll
            for (int i = 0; i < NB; i++) ssum += H[i * NB + c];
            cs[c] = (float)ssum;
        }
        __syncthreads();
        double acc = 0.0;
        int begin = half * 450;
        for (int idx = begin + tid; idx < begin + 450; idx += blockDim.x) {
            int i = idx / NB, j = idx % NB;
            float cnt = (float)H[idx];
            float pxy = (cnt > 0.f) ? __fdiv_rn(cnt, n_total) : 1e-10f;
            float px  = (rs[i] > 0.f) ? __fdiv_rn(rs[i], n_total) : 1e-10f;
            float py  = (cs[j] > 0.f) ? __fdiv_rn(cs[j], n_total) : 1e-10f;
            acc += (double)(pxy * logf(pxy / (px * py)));
        }
#pragma unroll
        for (int o = 16; o; o >>= 1) acc += __shfl_down_sync(0xFFFFFFFFu, acc, o);
        double* wacc = (double*)(sh + 64);
        __shared__ int zeroer;
        if ((tid & 31) == 0) wacc[tid >> 5] = acc;
        __syncthreads();
        if (tid == 0) {
            double sum = 0.0;
            for (int w = 0; w < 8; w++) sum += wacc[w];
            atomicAdd(&g_mi_hist, sum);
            zeroer = (atomicAdd(&g_hdone[h], 1u) == 1u);  // second finisher resets this hist
        }
        __syncthreads();
        if (zeroer) {
            for (int w = tid; w < NB * NB; w += blockDim.x) H[w] = 0u;
            if (tid == 0) g_hdone[h] = 0u;
        }
    } else {
        int i = bid - 64;
        int* slu = (int*)sh;
        int* sls = (int*)sh + 16;
        if (tid == 0) {
            float uv[16];
#pragma unroll
            for (int d = 0; d < 16; d++) uv[d] = u[i * 16 + d];
            labelize16(uv, slu);
        } else if (tid == 32) {
            float sv[16];
#pragma unroll
            for (int d = 0; d < 16; d++) sv[d] = s[i * 16 + d];
            labelize16(sv, sls);
        }
        __syncthreads();
        float term = 0.f;
        if (tid < 16) {
            int lj = slu[tid], sj = sls[tid];
            int a2 = 0, b2 = 0, c2 = 0;
#pragma unroll
            for (int k = 0; k < 16; k++) {
                int eu = (slu[k] == lj);
                int es = (sls[k] == sj);
                a2 += eu; b2 += es; c2 += eu & es;
            }
            term = logf((float)(c2 * 16) / (float)(a2 * b2));
        }
        if (tid < 32) {
            double acc = (double)term;
#pragma unroll
            for (int o = 16; o; o >>= 1) acc += __shfl_down_sync(0xFFFFFFFFu, acc, o);
            if (tid == 0) atomicAdd(&g_mi_us, acc * (1.0 / 16.0));
        }
    }

    // ---------- combine + full state reset (last fin block) ----------
    __threadfence();
    __syncthreads();
    if (tid == 0) {
        unsigned ticket = atomicAdd(&g_done, 1u);
        if (ticket == FIN_BLOCKS - 1u) {
            out[0] = (float)(g_l1sum / (double)n_total + 0.1 * g_mi_hist - 0.05 * g_mi_us);
            for (int i = 0; i < 33; i++) { g_maxkey[i] = 0u; g_minkey[i] = 0u; }
            g_l1sum = 0.0; g_mi_hist = 0.0; g_mi_us = 0.0;
            g_arrive1 = 0u; g_arrive2 = 0u;
            __threadfence();
            g_done = 0u;
        }
    }
}

// ---------------- launch ----------------
extern "C" void kernel_launch(void* const* d_in, const int* in_sizes, int n_in,
                              void* d_out, int out_size) {
    const float* y_true = (const float*)d_in[0];
    const float* y_pred = (const float*)d_in[1];
    const float* u_vec  = (const float*)d_in[4];
    const float* s_vec  = (const float*)d_in[5];
    int n = in_sizes[0];

    k_main<<<GRID_MAIN, 256>>>(u_vec, s_vec, y_true, y_pred, n, (float)n, (float*)d_out);
}